// round 2
// baseline (speedup 1.0000x reference)
#include <cuda_runtime.h>

#define NGROUPS 16384
#define NG 16
#define PH 64
#define PB 32   // PH/2 packed blocks
#define AH 12
#define AB 6    // AH/2 packed blocks
#define MD 48
#define GRID 1024
#define BLOCK 256

typedef unsigned long long ull;

__device__ __forceinline__ ull pk2(float lo, float hi) {
    ull r; asm("mov.b64 %0, {%1, %2};" : "=l"(r) : "f"(lo), "f"(hi)); return r;
}
__device__ __forceinline__ void upk2(ull p, float& a, float& b) {
    asm("mov.b64 {%0, %1}, %2;" : "=f"(a), "=f"(b) : "l"(p));
}
__device__ __forceinline__ ull fma2(ull a, ull b, ull c) {
    ull d; asm("fma.rn.f32x2 %0, %1, %2, %3;" : "=l"(d) : "l"(a), "l"(b), "l"(c)); return d;
}
__device__ __forceinline__ ull relu2(ull p) {
    float a, b; upk2(p, a, b);
    return pk2(fmaxf(a, 0.0f), fmaxf(b, 0.0f));
}

struct __align__(16) SM {
    float pos_tab[PB * 16];   // per 2-hidden block: w1x2,w1y2,w1z2,b2,w20_2,w21_2,w22_2,pad2
    float attn_tab[AB * 16];
    float mw1[MD * MD];
    float mw2[MD * MD];
    float mw3[MD];
    float mb1[MD];
    float mb2[MD];
    float wqkv[28];
    float pb2v[4];
    float ab2v[4];
    float mb3;
    float pad0[3];
    // per-group scratch
    float xs[48];
    float qs[48];
    float ks_[48];
    float vs[48];
    float sa[MD];
    float h1[MD];
    float h2[MD];
};

__global__ void __launch_bounds__(BLOCK, 4) pt_kernel(
    const float* __restrict__ data,
    const float* __restrict__ wqkv,
    const float* __restrict__ pw1, const float* __restrict__ pb1,
    const float* __restrict__ pw2, const float* __restrict__ pb2,
    const float* __restrict__ aw1, const float* __restrict__ ab1,
    const float* __restrict__ aw2, const float* __restrict__ ab2,
    const float* __restrict__ mw1, const float* __restrict__ mb1,
    const float* __restrict__ mw2, const float* __restrict__ mb2,
    const float* __restrict__ mw3, const float* __restrict__ mb3,
    float* __restrict__ out)
{
    __shared__ SM s;
    const int t = threadIdx.x;

    // ---- load weights into shared (once per CTA) ----
    for (int idx = t; idx < PB; idx += BLOCK) {
        int k = 2 * idx; float* b = &s.pos_tab[idx * 16];
        b[0]  = pw1[k];          b[1]  = pw1[k + 1];
        b[2]  = pw1[64 + k];     b[3]  = pw1[64 + k + 1];
        b[4]  = pw1[128 + k];    b[5]  = pw1[128 + k + 1];
        b[6]  = pb1[k];          b[7]  = pb1[k + 1];
        b[8]  = pw2[3 * k + 0];  b[9]  = pw2[3 * k + 3];
        b[10] = pw2[3 * k + 1];  b[11] = pw2[3 * k + 4];
        b[12] = pw2[3 * k + 2];  b[13] = pw2[3 * k + 5];
        b[14] = 0.0f;            b[15] = 0.0f;
    }
    for (int idx = t; idx < AB; idx += BLOCK) {
        int k = 2 * idx; float* b = &s.attn_tab[idx * 16];
        b[0]  = aw1[k];          b[1]  = aw1[k + 1];
        b[2]  = aw1[12 + k];     b[3]  = aw1[12 + k + 1];
        b[4]  = aw1[24 + k];     b[5]  = aw1[24 + k + 1];
        b[6]  = ab1[k];          b[7]  = ab1[k + 1];
        b[8]  = aw2[3 * k + 0];  b[9]  = aw2[3 * k + 3];
        b[10] = aw2[3 * k + 1];  b[11] = aw2[3 * k + 4];
        b[12] = aw2[3 * k + 2];  b[13] = aw2[3 * k + 5];
        b[14] = 0.0f;            b[15] = 0.0f;
    }
    for (int idx = t; idx < MD * MD; idx += BLOCK) {
        s.mw1[idx] = mw1[idx];
        s.mw2[idx] = mw2[idx];
    }
    if (t < MD) { s.mw3[t] = mw3[t]; s.mb1[t] = mb1[t]; s.mb2[t] = mb2[t]; }
    if (t < 27) s.wqkv[t] = wqkv[t];
    if (t < 3)  { s.pb2v[t] = pb2[t]; s.ab2v[t] = ab2[t]; }
    if (t == 0) s.mb3 = mb3[0];
    __syncthreads();

    const int i = t >> 4;
    const int j = t & 15;

    for (int g = blockIdx.x; g < NGROUPS; g += gridDim.x) {
        // ---- load group points ----
        if (t < 48) s.xs[t] = data[(size_t)g * 48 + t];
        __syncthreads();

        // ---- qkv = x @ w_qkv ----
        if (t < NG) {
            float x0 = s.xs[t * 3], x1 = s.xs[t * 3 + 1], x2 = s.xs[t * 3 + 2];
            #pragma unroll
            for (int c = 0; c < 3; c++) {
                s.qs[t * 3 + c]  = x0 * s.wqkv[c]     + x1 * s.wqkv[9 + c]  + x2 * s.wqkv[18 + c];
                s.ks_[t * 3 + c] = x0 * s.wqkv[3 + c] + x1 * s.wqkv[12 + c] + x2 * s.wqkv[21 + c];
                s.vs[t * 3 + c]  = x0 * s.wqkv[6 + c] + x1 * s.wqkv[15 + c] + x2 * s.wqkv[24 + c];
            }
        }
        __syncthreads();

        // ---- per-pair (i,j) work ----
        float rx = s.xs[i * 3]     - s.xs[j * 3];
        float ry = s.xs[i * 3 + 1] - s.xs[j * 3 + 1];
        float rz = s.xs[i * 3 + 2] - s.xs[j * 3 + 2];
        ull rx2 = pk2(rx, rx), ry2 = pk2(ry, ry), rz2 = pk2(rz, rz);

        // pos MLP: 3 -> 64 -> 3, packed f32x2
        ull a0 = 0ull, a1 = 0ull, a2 = 0ull;
        const ulonglong2* pt = (const ulonglong2*)s.pos_tab;
        #pragma unroll
        for (int kb = 0; kb < PB; kb++) {
            ulonglong2 t0 = pt[kb * 4 + 0];
            ulonglong2 t1 = pt[kb * 4 + 1];
            ulonglong2 t2 = pt[kb * 4 + 2];
            ulonglong2 t3 = pt[kb * 4 + 3];
            ull h = fma2(rx2, t0.x, fma2(ry2, t0.y, fma2(rz2, t1.x, t1.y)));
            h = relu2(h);
            a0 = fma2(h, t2.x, a0);
            a1 = fma2(h, t2.y, a1);
            a2 = fma2(h, t3.x, a2);
        }
        float ua, ub;
        upk2(a0, ua, ub); float re0 = ua + ub + s.pb2v[0];
        upk2(a1, ua, ub); float re1 = ua + ub + s.pb2v[1];
        upk2(a2, ua, ub); float re2 = ua + ub + s.pb2v[2];

        float vj0 = s.vs[j * 3]     + re0;
        float vj1 = s.vs[j * 3 + 1] + re1;
        float vj2 = s.vs[j * 3 + 2] + re2;
        float ex = s.qs[i * 3]     - s.ks_[j * 3]     + re0;
        float ey = s.qs[i * 3 + 1] - s.ks_[j * 3 + 1] + re1;
        float ez = s.qs[i * 3 + 2] - s.ks_[j * 3 + 2] + re2;
        ull ex2 = pk2(ex, ex), ey2 = pk2(ey, ey), ez2 = pk2(ez, ez);

        // attn MLP: 3 -> 12 -> 3
        ull b0 = 0ull, b1 = 0ull, b2 = 0ull;
        const ulonglong2* at = (const ulonglong2*)s.attn_tab;
        #pragma unroll
        for (int kb = 0; kb < AB; kb++) {
            ulonglong2 t0 = at[kb * 4 + 0];
            ulonglong2 t1 = at[kb * 4 + 1];
            ulonglong2 t2 = at[kb * 4 + 2];
            ulonglong2 t3 = at[kb * 4 + 3];
            ull h = fma2(ex2, t0.x, fma2(ey2, t0.y, fma2(ez2, t1.x, t1.y)));
            h = relu2(h);
            b0 = fma2(h, t2.x, b0);
            b1 = fma2(h, t2.y, b1);
            b2 = fma2(h, t3.x, b2);
        }
        upk2(b0, ua, ub); float s0 = ua + ub + s.ab2v[0];
        upk2(b1, ua, ub); float s1 = ua + ub + s.ab2v[1];
        upk2(b2, ua, ub); float s2 = ua + ub + s.ab2v[2];

        // ---- softmax over j within 16-lane segment ----
        float m0 = s0, m1 = s1, m2 = s2;
        #pragma unroll
        for (int d_ = 8; d_; d_ >>= 1) {
            m0 = fmaxf(m0, __shfl_xor_sync(0xffffffffu, m0, d_));
            m1 = fmaxf(m1, __shfl_xor_sync(0xffffffffu, m1, d_));
            m2 = fmaxf(m2, __shfl_xor_sync(0xffffffffu, m2, d_));
        }
        float p0 = __expf(s0 - m0), p1 = __expf(s1 - m1), p2 = __expf(s2 - m2);
        float z0 = p0, z1 = p1, z2 = p2;
        #pragma unroll
        for (int d_ = 8; d_; d_ >>= 1) {
            z0 += __shfl_xor_sync(0xffffffffu, z0, d_);
            z1 += __shfl_xor_sync(0xffffffffu, z1, d_);
            z2 += __shfl_xor_sync(0xffffffffu, z2, d_);
        }
        float g0 = p0 * vj0 * __fdividef(1.0f, z0);
        float g1 = p1 * vj1 * __fdividef(1.0f, z1);
        float g2 = p2 * vj2 * __fdividef(1.0f, z2);
        #pragma unroll
        for (int d_ = 8; d_; d_ >>= 1) {
            g0 += __shfl_xor_sync(0xffffffffu, g0, d_);
            g1 += __shfl_xor_sync(0xffffffffu, g1, d_);
            g2 += __shfl_xor_sync(0xffffffffu, g2, d_);
        }
        if (j == 0) {
            s.sa[i * 3]     = g0;
            s.sa[i * 3 + 1] = g1;
            s.sa[i * 3 + 2] = g2;
        }
        __syncthreads();

        // ---- output MLP: 48 -> 48 -> 48 -> 1 ----
        if (t < MD) {
            float acc = s.mb1[t];
            #pragma unroll
            for (int k2 = 0; k2 < MD; k2++) acc += s.sa[k2] * s.mw1[k2 * MD + t];
            s.h1[t] = fmaxf(acc, 0.0f);
        }
        __syncthreads();
        if (t < MD) {
            float acc = s.mb2[t];
            #pragma unroll
            for (int k2 = 0; k2 < MD; k2++) acc += s.h1[k2] * s.mw2[k2 * MD + t];
            s.h2[t] = fmaxf(acc, 0.0f);
        }
        __syncthreads();
        if (t < 32) {
            float p = s.h2[t] * s.mw3[t];
            if (t < 16) p += s.h2[t + 32] * s.mw3[t + 32];
            #pragma unroll
            for (int d_ = 16; d_; d_ >>= 1) p += __shfl_xor_sync(0xffffffffu, p, d_);
            if (t == 0) out[g] = p + s.mb3;
        }
        __syncthreads();
    }
}

extern "C" void kernel_launch(void* const* d_in, const int* in_sizes, int n_in,
                              void* d_out, int out_size) {
    // inputs (metadata order):
    // 0 original_points (unused), 1 data, 2 w_qkv, 3 pos_w1, 4 pos_b1,
    // 5 pos_w2, 6 pos_b2, 7 attn_w1, 8 attn_b1, 9 attn_w2, 10 attn_b2,
    // 11 mlp_w1, 12 mlp_b1, 13 mlp_w2, 14 mlp_b2, 15 mlp_w3, 16 mlp_b3
    pt_kernel<<<GRID, BLOCK>>>(
        (const float*)d_in[1],
        (const float*)d_in[2],
        (const float*)d_in[3], (const float*)d_in[4],
        (const float*)d_in[5], (const float*)d_in[6],
        (const float*)d_in[7], (const float*)d_in[8],
        (const float*)d_in[9], (const float*)d_in[10],
        (const float*)d_in[11], (const float*)d_in[12],
        (const float*)d_in[13], (const float*)d_in[14],
        (const float*)d_in[15], (const float*)d_in[16],
        (float*)d_out);
}

// round 3
// speedup vs baseline: 1.4344x; 1.4344x over previous
#include <cuda_runtime.h>

#define NGROUPS 16384
#define NG 16
#define MD 48
#define GRID 1024
#define BLOCK 256

typedef unsigned long long ull;

__device__ __forceinline__ ull pk2(float lo, float hi) {
    ull r; asm("mov.b64 %0, {%1, %2};" : "=l"(r) : "f"(lo), "f"(hi)); return r;
}
__device__ __forceinline__ void upk2(ull p, float& a, float& b) {
    asm("mov.b64 {%0, %1}, %2;" : "=f"(a), "=f"(b) : "l"(p));
}
__device__ __forceinline__ ull fma2(ull a, ull b, ull c) {
    ull d; asm("fma.rn.f32x2 %0, %1, %2, %3;" : "=l"(d) : "l"(a), "l"(b), "l"(c)); return d;
}
__device__ __forceinline__ ull relu2(ull p) {
    float a, b; upk2(p, a, b);
    return pk2(fmaxf(a, 0.0f), fmaxf(b, 0.0f));
}
__device__ __forceinline__ float sum2(ull p) {
    float a, b; upk2(p, a, b); return a + b;
}

// pos MLP packed: 16 superblocks of 4 hidden units, 7 ulonglong2 (28 floats) each:
//   [w1x(4), w1y(4), w1z(4), b1(4), w2c0(4), w2c1(4), w2c2(4)]
// attn MLP: 3 superblocks, same format.
struct __align__(16) SM {
    float4 xs4[2][16];
    float4 qs4[2][16];
    float4 ks4[2][16];
    float4 vs4[2][16];
    float pos7[16 * 28];   // 448
    float attn7[3 * 28];   // 84, starts 16B-aligned (448*4 % 16 == 0)
    float pad_a[4];        // keep following data 16B aligned
    float mw1[MD * MD];
    float mw2[MD * MD];
    float mw3[MD];
    float mb1[MD];
    float mb2[MD];
    float wqkv[27];
    float pb2v[3];
    float ab2v[3];
    float mb3;
    float sa[2][MD];
    float h1[2][MD];
    float h2[2][MD];
};

__global__ void __launch_bounds__(BLOCK, 2) pt_kernel(
    const float* __restrict__ data,
    const float* __restrict__ wqkv,
    const float* __restrict__ pw1, const float* __restrict__ pb1,
    const float* __restrict__ pw2, const float* __restrict__ pb2,
    const float* __restrict__ aw1, const float* __restrict__ ab1,
    const float* __restrict__ aw2, const float* __restrict__ ab2,
    const float* __restrict__ mw1, const float* __restrict__ mb1,
    const float* __restrict__ mw2, const float* __restrict__ mb2,
    const float* __restrict__ mw3, const float* __restrict__ mb3,
    float* __restrict__ out)
{
    __shared__ SM s;
    const int t = threadIdx.x;

    // ---- fill weight tables (once per CTA) ----
    if (t < 16) {
        int u = 4 * t; float* b = &s.pos7[t * 28];
        #pragma unroll
        for (int q = 0; q < 4; q++) {
            b[q]      = pw1[u + q];
            b[4 + q]  = pw1[64 + u + q];
            b[8 + q]  = pw1[128 + u + q];
            b[12 + q] = pb1[u + q];
            b[16 + q] = pw2[3 * (u + q) + 0];
            b[20 + q] = pw2[3 * (u + q) + 1];
            b[24 + q] = pw2[3 * (u + q) + 2];
        }
    }
    if (t >= 16 && t < 19) {
        int sb = t - 16;
        int u = 4 * sb; float* b = &s.attn7[sb * 28];
        #pragma unroll
        for (int q = 0; q < 4; q++) {
            b[q]      = aw1[u + q];
            b[4 + q]  = aw1[12 + u + q];
            b[8 + q]  = aw1[24 + u + q];
            b[12 + q] = ab1[u + q];
            b[16 + q] = aw2[3 * (u + q) + 0];
            b[20 + q] = aw2[3 * (u + q) + 1];
            b[24 + q] = aw2[3 * (u + q) + 2];
        }
    }
    for (int idx = t; idx < MD * MD; idx += BLOCK) {
        s.mw1[idx] = mw1[idx];
        s.mw2[idx] = mw2[idx];
    }
    if (t < MD) { s.mw3[t] = mw3[t]; s.mb1[t] = mb1[t]; s.mb2[t] = mb2[t]; }
    if (t >= 64 && t < 91) s.wqkv[t - 64] = wqkv[t - 64];
    if (t >= 96 && t < 99) { s.pb2v[t - 96] = pb2[t - 96]; s.ab2v[t - 96] = ab2[t - 96]; }
    if (t == 128) s.mb3 = mb3[0];
    __syncthreads();

    const int i = t >> 4;
    const int j = t & 15;

    for (int gi = blockIdx.x; gi < NGROUPS / 2; gi += gridDim.x) {
        const size_t gbase = (size_t)gi * 96;

        // ---- load points for 2 groups (coalesced), pad to float4 ----
        if (t < 96) {
            int gg = t / 48, r = t % 48;
            ((float*)&s.xs4[gg][r / 3])[r % 3] = data[gbase + t];
        }
        __syncthreads();

        // ---- qkv (t<32: gg = t>>4, point p = t&15) ----
        if (t < 32) {
            int gg = t >> 4, p = t & 15;
            float4 x = s.xs4[gg][p];
            float q0, q1, q2, k0, k1, k2, v0, v1, v2;
            q0 = x.x * s.wqkv[0] + x.y * s.wqkv[9]  + x.z * s.wqkv[18];
            q1 = x.x * s.wqkv[1] + x.y * s.wqkv[10] + x.z * s.wqkv[19];
            q2 = x.x * s.wqkv[2] + x.y * s.wqkv[11] + x.z * s.wqkv[20];
            k0 = x.x * s.wqkv[3] + x.y * s.wqkv[12] + x.z * s.wqkv[21];
            k1 = x.x * s.wqkv[4] + x.y * s.wqkv[13] + x.z * s.wqkv[22];
            k2 = x.x * s.wqkv[5] + x.y * s.wqkv[14] + x.z * s.wqkv[23];
            v0 = x.x * s.wqkv[6] + x.y * s.wqkv[15] + x.z * s.wqkv[24];
            v1 = x.x * s.wqkv[7] + x.y * s.wqkv[16] + x.z * s.wqkv[25];
            v2 = x.x * s.wqkv[8] + x.y * s.wqkv[17] + x.z * s.wqkv[26];
            s.qs4[gg][p] = make_float4(q0, q1, q2, 0.f);
            s.ks4[gg][p] = make_float4(k0, k1, k2, 0.f);
            s.vs4[gg][p] = make_float4(v0, v1, v2, 0.f);
        }

        // ---- rel pos for both groups ----
        ull rx2[2], ry2[2], rz2[2];
        #pragma unroll
        for (int gg = 0; gg < 2; gg++) {
            float4 xi = s.xs4[gg][i];
            float4 xj = s.xs4[gg][j];
            float rx = xi.x - xj.x, ry = xi.y - xj.y, rz = xi.z - xj.z;
            rx2[gg] = pk2(rx, rx); ry2[gg] = pk2(ry, ry); rz2[gg] = pk2(rz, rz);
        }

        // ---- pos MLP 3->64->3 for both groups, weights loaded once ----
        ull a0[2] = {0ull, 0ull}, a1[2] = {0ull, 0ull}, a2[2] = {0ull, 0ull};
        const ulonglong2* P7 = (const ulonglong2*)s.pos7;
        #pragma unroll
        for (int sb = 0; sb < 16; sb++) {
            ulonglong2 v0 = P7[sb * 7 + 0];
            ulonglong2 v1 = P7[sb * 7 + 1];
            ulonglong2 v2 = P7[sb * 7 + 2];
            ulonglong2 v3 = P7[sb * 7 + 3];
            ulonglong2 v4 = P7[sb * 7 + 4];
            ulonglong2 v5 = P7[sb * 7 + 5];
            ulonglong2 v6 = P7[sb * 7 + 6];
            #pragma unroll
            for (int gg = 0; gg < 2; gg++) {
                ull hA = relu2(fma2(rx2[gg], v0.x, fma2(ry2[gg], v1.x, fma2(rz2[gg], v2.x, v3.x))));
                ull hB = relu2(fma2(rx2[gg], v0.y, fma2(ry2[gg], v1.y, fma2(rz2[gg], v2.y, v3.y))));
                a0[gg] = fma2(hA, v4.x, fma2(hB, v4.y, a0[gg]));
                a1[gg] = fma2(hA, v5.x, fma2(hB, v5.y, a1[gg]));
                a2[gg] = fma2(hA, v6.x, fma2(hB, v6.y, a2[gg]));
            }
        }
        __syncthreads();   // qkv writes now visible; everyone reached uniformly

        float re0[2], re1[2], re2[2];
        float vj0[2], vj1[2], vj2[2];
        ull ex2[2], ey2[2], ez2[2];
        #pragma unroll
        for (int gg = 0; gg < 2; gg++) {
            re0[gg] = sum2(a0[gg]) + s.pb2v[0];
            re1[gg] = sum2(a1[gg]) + s.pb2v[1];
            re2[gg] = sum2(a2[gg]) + s.pb2v[2];
            float4 qi = s.qs4[gg][i];
            float4 kj = s.ks4[gg][j];
            float4 vj = s.vs4[gg][j];
            vj0[gg] = vj.x + re0[gg];
            vj1[gg] = vj.y + re1[gg];
            vj2[gg] = vj.z + re2[gg];
            float ex = qi.x - kj.x + re0[gg];
            float ey = qi.y - kj.y + re1[gg];
            float ez = qi.z - kj.z + re2[gg];
            ex2[gg] = pk2(ex, ex); ey2[gg] = pk2(ey, ey); ez2[gg] = pk2(ez, ez);
        }

        // ---- attn MLP 3->12->3 for both groups ----
        ull b0[2] = {0ull, 0ull}, b1[2] = {0ull, 0ull}, b2[2] = {0ull, 0ull};
        const ulonglong2* A7 = (const ulonglong2*)s.attn7;
        #pragma unroll
        for (int sb = 0; sb < 3; sb++) {
            ulonglong2 v0 = A7[sb * 7 + 0];
            ulonglong2 v1 = A7[sb * 7 + 1];
            ulonglong2 v2 = A7[sb * 7 + 2];
            ulonglong2 v3 = A7[sb * 7 + 3];
            ulonglong2 v4 = A7[sb * 7 + 4];
            ulonglong2 v5 = A7[sb * 7 + 5];
            ulonglong2 v6 = A7[sb * 7 + 6];
            #pragma unroll
            for (int gg = 0; gg < 2; gg++) {
                ull hA = relu2(fma2(ex2[gg], v0.x, fma2(ey2[gg], v1.x, fma2(ez2[gg], v2.x, v3.x))));
                ull hB = relu2(fma2(ex2[gg], v0.y, fma2(ey2[gg], v1.y, fma2(ez2[gg], v2.y, v3.y))));
                b0[gg] = fma2(hA, v4.x, fma2(hB, v4.y, b0[gg]));
                b1[gg] = fma2(hA, v5.x, fma2(hB, v5.y, b1[gg]));
                b2[gg] = fma2(hA, v6.x, fma2(hB, v6.y, b2[gg]));
            }
        }

        // ---- softmax over j (16-lane segments), no max-subtract; fused z & p*v sums ----
        float z0[2], z1[2], z2[2], g0[2], g1[2], g2[2];
        #pragma unroll
        for (int gg = 0; gg < 2; gg++) {
            float s0 = sum2(b0[gg]) + s.ab2v[0];
            float s1 = sum2(b1[gg]) + s.ab2v[1];
            float s2 = sum2(b2[gg]) + s.ab2v[2];
            float p0 = __expf(s0), p1 = __expf(s1), p2 = __expf(s2);
            z0[gg] = p0; z1[gg] = p1; z2[gg] = p2;
            g0[gg] = p0 * vj0[gg]; g1[gg] = p1 * vj1[gg]; g2[gg] = p2 * vj2[gg];
        }
        #pragma unroll
        for (int d_ = 8; d_; d_ >>= 1) {
            #pragma unroll
            for (int gg = 0; gg < 2; gg++) {
                z0[gg] += __shfl_xor_sync(0xffffffffu, z0[gg], d_);
                z1[gg] += __shfl_xor_sync(0xffffffffu, z1[gg], d_);
                z2[gg] += __shfl_xor_sync(0xffffffffu, z2[gg], d_);
                g0[gg] += __shfl_xor_sync(0xffffffffu, g0[gg], d_);
                g1[gg] += __shfl_xor_sync(0xffffffffu, g1[gg], d_);
                g2[gg] += __shfl_xor_sync(0xffffffffu, g2[gg], d_);
            }
        }
        if (j == 0) {
            #pragma unroll
            for (int gg = 0; gg < 2; gg++) {
                s.sa[gg][i * 3]     = __fdividef(g0[gg], z0[gg]);
                s.sa[gg][i * 3 + 1] = __fdividef(g1[gg], z1[gg]);
                s.sa[gg][i * 3 + 2] = __fdividef(g2[gg], z2[gg]);
            }
        }
        __syncthreads();

        // ---- output MLP 48 -> 48 -> 48 -> 1, both groups (96 active threads) ----
        if (t < 96) {
            int gg = t / MD, u = t % MD;
            float acc = s.mb1[u];
            #pragma unroll
            for (int k2 = 0; k2 < MD; k2++) acc += s.sa[gg][k2] * s.mw1[k2 * MD + u];
            s.h1[gg][u] = fmaxf(acc, 0.0f);
        }
        __syncthreads();
        if (t < 96) {
            int gg = t / MD, u = t % MD;
            float acc = s.mb2[u];
            #pragma unroll
            for (int k2 = 0; k2 < MD; k2++) acc += s.h1[gg][k2] * s.mw2[k2 * MD + u];
            s.h2[gg][u] = fmaxf(acc, 0.0f);
        }
        __syncthreads();
        if (t < 64) {
            int gg = t >> 5, lane = t & 31;
            float p = s.h2[gg][lane] * s.mw3[lane];
            if (lane < 16) p += s.h2[gg][lane + 32] * s.mw3[lane + 32];
            #pragma unroll
            for (int d_ = 16; d_; d_ >>= 1) p += __shfl_xor_sync(0xffffffffu, p, d_);
            if (lane == 0) out[2 * gi + gg] = p + s.mb3;
        }
        __syncthreads();
    }
}

extern "C" void kernel_launch(void* const* d_in, const int* in_sizes, int n_in,
                              void* d_out, int out_size) {
    // 0 original_points (unused), 1 data, 2 w_qkv, 3 pos_w1, 4 pos_b1,
    // 5 pos_w2, 6 pos_b2, 7 attn_w1, 8 attn_b1, 9 attn_w2, 10 attn_b2,
    // 11 mlp_w1, 12 mlp_b1, 13 mlp_w2, 14 mlp_b2, 15 mlp_w3, 16 mlp_b3
    pt_kernel<<<GRID, BLOCK>>>(
        (const float*)d_in[1],
        (const float*)d_in[2],
        (const float*)d_in[3], (const float*)d_in[4],
        (const float*)d_in[5], (const float*)d_in[6],
        (const float*)d_in[7], (const float*)d_in[8],
        (const float*)d_in[9], (const float*)d_in[10],
        (const float*)d_in[11], (const float*)d_in[12],
        (const float*)d_in[13], (const float*)d_in[14],
        (const float*)d_in[15], (const float*)d_in[16],
        (float*)d_out);
}